// round 1
// baseline (speedup 1.0000x reference)
#include <cuda_runtime.h>

#define BATCH 262144
#define NBLOCKS 8192
#define BLOCK 128
#define WPB 4          // warps per block
#define ROWP 12        // padded row length (floats), 48B rows, 16B aligned
#define STSTRIDE 36    // score-transpose row stride (floats), 144B, 16B aligned

using u64 = unsigned long long;

__device__ __forceinline__ u64 fmul2(u64 a, u64 b) {
    u64 d; asm("mul.rn.f32x2 %0,%1,%2;" : "=l"(d) : "l"(a), "l"(b)); return d;
}
__device__ __forceinline__ u64 ffma2(u64 a, u64 b, u64 c) {
    u64 d; asm("fma.rn.f32x2 %0,%1,%2,%3;" : "=l"(d) : "l"(a), "l"(b), "l"(c)); return d;
}
__device__ __forceinline__ u64 fadd2(u64 a, u64 b) {
    u64 d; asm("add.rn.f32x2 %0,%1,%2;" : "=l"(d) : "l"(a), "l"(b)); return d;
}
__device__ __forceinline__ float hsum2(u64 a) {
    float lo, hi; asm("mov.b64 {%0,%1},%2;" : "=f"(lo), "=f"(hi) : "l"(a)); return lo + hi;
}
__device__ __forceinline__ u64 pack2(float lo, float hi) {
    u64 d; asm("mov.b64 %0,{%1,%2};" : "=l"(d) : "f"(lo), "f"(hi)); return d;
}

struct R5 { u64 p0, p1, p2, p3, p4; };

// Load a padded row (10 valid floats, 12 stored) as 5 packed f32x2 operands.
__device__ __forceinline__ R5 loadRow(const float* row) {
    R5 r;
    ulonglong2 a = *reinterpret_cast<const ulonglong2*>(row);      // floats 0..3
    ulonglong2 b = *reinterpret_cast<const ulonglong2*>(row + 4);  // floats 4..7
    u64 c = *reinterpret_cast<const u64*>(row + 8);                // floats 8..9
    r.p0 = a.x; r.p1 = a.y; r.p2 = b.x; r.p3 = b.y; r.p4 = c;
    return r;
}

// 10-element dot product: 5 packed FMA2 + 1 horizontal add.
__device__ __forceinline__ float dotR(const R5& a, const R5& b) {
    u64 x = fmul2(a.p0, b.p0);
    x = ffma2(a.p1, b.p1, x);
    x = ffma2(a.p2, b.p2, x);
    x = ffma2(a.p3, b.p3, x);
    x = ffma2(a.p4, b.p4, x);
    return hsum2(x);
}

__global__ void __launch_bounds__(BLOCK)
aie_kernel(const float* __restrict__ user_rep,
           const float* __restrict__ item_rep,
           const float* __restrict__ Mmat,
           const float* __restrict__ Pu,
           const float* __restrict__ pu_par,
           const float* __restrict__ Pi,
           const float* __restrict__ pi_par,
           float* __restrict__ out)
{
    __shared__ __align__(16) float MT[10 * ROWP];           // M transposed: MT[e][d]
    __shared__ __align__(16) float Us [WPB][10 * ROWP];     // U rows (per warp)
    __shared__ __align__(16) float Vs [WPB][10 * ROWP];     // V rows
    __shared__ __align__(16) float UMs[WPB][10 * ROWP];     // U @ M rows
    __shared__ __align__(16) float AF [WPB][10 * ROWP];     // aff[u][v]
    __shared__ __align__(16) float AFT[WPB][10 * ROWP];     // aff[v][u] (transposed)
    __shared__ __align__(16) float ST [WPB][20 * STSTRIDE]; // score transpose [20][32+pad]

    const int tid  = threadIdx.x;
    const int w    = tid >> 5;
    const int lane = tid & 31;

    // ---- one-time init: zero pads + build MT ----
    for (int i = tid; i < 10 * ROWP; i += BLOCK) MT[i] = 0.f;
    for (int i = lane; i < 10 * ROWP; i += 32) {
        Us[w][i] = 0.f; Vs[w][i] = 0.f; UMs[w][i] = 0.f; AF[w][i] = 0.f; AFT[w][i] = 0.f;
    }
    __syncthreads();
    if (tid < 100) MT[(tid % 10) * ROWP + (tid / 10)] = Mmat[tid];
    __syncthreads();

    // ---- per-lane persistent state: projection row k (packed), parameters ----
    R5 pu2, pi2;
    {
        const float* pr = Pu + lane * 10;
        pu2.p0 = pack2(pr[0], pr[1]); pu2.p1 = pack2(pr[2], pr[3]);
        pu2.p2 = pack2(pr[4], pr[5]); pu2.p3 = pack2(pr[6], pr[7]);
        pu2.p4 = pack2(pr[8], pr[9]);
        const float* qr = Pi + lane * 10;
        pi2.p0 = pack2(qr[0], qr[1]); pi2.p1 = pack2(qr[2], qr[3]);
        pi2.p2 = pack2(qr[4], qr[5]); pi2.p3 = pack2(qr[6], qr[7]);
        pi2.p4 = pack2(qr[8], qr[9]);
    }
    const float puk = pu_par[lane];
    const float pik = pi_par[lane];

    // ---- phase-A scatter offsets (float4 chunk -> padded rows), fixed per lane ----
    int aoff0, aoff1, aoff2, aoff3;
    {
        int i0 = lane * 4;
        aoff0 = (i0 / 10) * ROWP + (i0 % 10);
        aoff1 = ((i0 + 1) / 10) * ROWP + ((i0 + 1) % 10);
        aoff2 = ((i0 + 2) / 10) * ROWP + ((i0 + 2) % 10);
        aoff3 = ((i0 + 3) / 10) * ROWP + ((i0 + 3) % 10);
    }
    const bool aload = (lane < 25);

    // ---- phase-B/C output assignment: outputs o = lane + 32*j, o<100 ----
    int rA[4], rB[4], oF[4], oT[4];
    const int nOut = (lane < 4) ? 4 : 3;
#pragma unroll
    for (int j = 0; j < 4; j++) {
        int o = lane + 32 * j;
        if (o > 99) o = 99;  // dummy (guarded by nOut)
        int u = o / 10, e = o % 10;
        rA[j] = u * ROWP;
        rB[j] = e * ROWP;
        oF[j] = u * ROWP + e;
        oT[j] = e * ROWP + u;
    }

    // score-reduction lane mapping: lanes 0-9 -> user rows 0-9, lanes 16-25 -> item rows 10-19
    const int sl = (lane < 10) ? lane : ((lane >= 16 && lane < 26) ? (lane - 6) : -1);

    const int gw     = blockIdx.x * WPB + w;
    const int stride = gridDim.x * WPB;

    for (int b = gw; b < BATCH; b += stride) {
        // ================= A: load U, V into padded smem rows =================
        if (aload) {
            float4 uq = reinterpret_cast<const float4*>(user_rep + (size_t)b * 100)[lane];
            float4 vq = reinterpret_cast<const float4*>(item_rep + (size_t)b * 100)[lane];
            float* Uw = Us[w]; float* Vw = Vs[w];
            Uw[aoff0] = uq.x; Uw[aoff1] = uq.y; Uw[aoff2] = uq.z; Uw[aoff3] = uq.w;
            Vw[aoff0] = vq.x; Vw[aoff1] = vq.y; Vw[aoff2] = vq.z; Vw[aoff3] = vq.w;
        }
        __syncwarp();

        // ================= B: UM[u][e] = dot(U[u,:], MT[e,:]) =================
#pragma unroll
        for (int j = 0; j < 4; j++) {
            if (j < nOut) {
                R5 a = loadRow(Us[w] + rA[j]);
                R5 m = loadRow(MT + rB[j]);
                UMs[w][oF[j]] = dotR(a, m);
            }
        }
        __syncwarp();

        // ======== C: aff[u][v] = relu(dot(UM[u,:], V[v,:])), + transpose ========
#pragma unroll
        for (int j = 0; j < 4; j++) {
            if (j < nOut) {
                R5 a = loadRow(UMs[w] + rA[j]);
                R5 v = loadRow(Vs[w] + rB[j]);
                float t = fmaxf(dotR(a, v), 0.f);
                AF[w][oF[j]]  = t;
                AFT[w][oT[j]] = t;
            }
        }
        __syncwarp();

        // ================= D/E: h_user[k=lane][u], h_item[k][v] =================
        float hU[10], hI[10];
#pragma unroll
        for (int u = 0; u < 10; u++) {
            R5 r = loadRow(Us[w] + u * ROWP);
            hU[u] = dotR(pu2, r);
        }
#pragma unroll
        for (int v = 0; v < 10; v++) {
            R5 r = loadRow(Vs[w] + v * ROWP);
            hI[v] = dotR(pi2, r);
        }
        R5 hU2, hI2;
        hU2.p0 = pack2(hU[0], hU[1]); hU2.p1 = pack2(hU[2], hU[3]);
        hU2.p2 = pack2(hU[4], hU[5]); hU2.p3 = pack2(hU[6], hU[7]);
        hU2.p4 = pack2(hU[8], hU[9]);
        hI2.p0 = pack2(hI[0], hI[1]); hI2.p1 = pack2(hI[2], hI[3]);
        hI2.p2 = pack2(hI[4], hI[5]); hI2.p3 = pack2(hI[6], hI[7]);
        hI2.p4 = pack2(hI[8], hI[9]);

        // === F/G: hu = relu(hU + hI . aff[u,:]),  hi = relu(hI + hU . aff[:,v]) ===
        float* STw = ST[w];
#pragma unroll
        for (int u = 0; u < 10; u++) {
            R5 r = loadRow(AF[w] + u * ROWP);
            float t = fmaxf(hU[u] + dotR(hI2, r), 0.f);
            STw[u * STSTRIDE + lane] = puk * t;
        }
#pragma unroll
        for (int v = 0; v < 10; v++) {
            R5 r = loadRow(AFT[w] + v * ROWP);
            float t = fmaxf(hI[v] + dotR(hU2, r), 0.f);
            STw[(10 + v) * STSTRIDE + lane] = pik * t;
        }
        __syncwarp();

        // ============== H: reduce over k (32 lanes) via smem transpose ==============
        float score = -1e30f;
        if (sl >= 0) {
            const ulonglong2* q = reinterpret_cast<const ulonglong2*>(STw + sl * STSTRIDE);
            u64 t0 = fadd2(q[0].x, q[0].y);
            u64 t1 = fadd2(q[1].x, q[1].y);
            u64 t2 = fadd2(q[2].x, q[2].y);
            u64 t3 = fadd2(q[3].x, q[3].y);
            u64 t4 = fadd2(q[4].x, q[4].y);
            u64 t5 = fadd2(q[5].x, q[5].y);
            u64 t6 = fadd2(q[6].x, q[6].y);
            u64 t7 = fadd2(q[7].x, q[7].y);
            t0 = fadd2(t0, t1); t2 = fadd2(t2, t3);
            t4 = fadd2(t4, t5); t6 = fadd2(t6, t7);
            t0 = fadd2(t0, t2); t4 = fadd2(t4, t6);
            score = hsum2(fadd2(t0, t4));
        }

        // softmax within 16-lane subgroups (user: lanes 0-15, item: lanes 16-31)
        float mv = score;
#pragma unroll
        for (int msk = 8; msk; msk >>= 1)
            mv = fmaxf(mv, __shfl_xor_sync(0xffffffffu, mv, msk));
        float ev = __expf(score - mv);
        float sv = ev;
#pragma unroll
        for (int msk = 8; msk; msk >>= 1)
            sv += __shfl_xor_sync(0xffffffffu, sv, msk);
        float res = __fdividef(ev, sv);

        if (lane < 10)
            out[(size_t)b * 10 + lane] = res;
        else if (lane >= 16 && lane < 26)
            out[(size_t)BATCH * 10 + (size_t)b * 10 + (lane - 16)] = res;
        __syncwarp();
    }
}

extern "C" void kernel_launch(void* const* d_in, const int* in_sizes, int n_in,
                              void* d_out, int out_size) {
    const float* user_rep = (const float*)d_in[0];
    const float* item_rep = (const float*)d_in[1];
    const float* M        = (const float*)d_in[2];
    const float* Pu       = (const float*)d_in[3];
    const float* pu       = (const float*)d_in[4];
    const float* Pi       = (const float*)d_in[5];
    const float* pi       = (const float*)d_in[6];
    (void)in_sizes; (void)n_in; (void)out_size;
    aie_kernel<<<NBLOCKS, BLOCK>>>(user_rep, item_rep, M, Pu, pu, Pi, pi, (float*)d_out);
}

// round 2
// speedup vs baseline: 1.4023x; 1.4023x over previous
#include <cuda_runtime.h>

#define BATCH 262144
#define NBLOCKS 8192
#define BLOCK 128
#define WPB 4
#define STSTRIDE 36

using u64 = unsigned long long;

__device__ __forceinline__ u64 fmul2(u64 a, u64 b) {
    u64 d; asm("mul.rn.f32x2 %0,%1,%2;" : "=l"(d) : "l"(a), "l"(b)); return d;
}
__device__ __forceinline__ u64 ffma2(u64 a, u64 b, u64 c) {
    u64 d; asm("fma.rn.f32x2 %0,%1,%2,%3;" : "=l"(d) : "l"(a), "l"(b), "l"(c)); return d;
}
__device__ __forceinline__ u64 fadd2(u64 a, u64 b) {
    u64 d; asm("add.rn.f32x2 %0,%1,%2;" : "=l"(d) : "l"(a), "l"(b)); return d;
}
__device__ __forceinline__ float hsum2(u64 a) {
    float lo, hi; asm("mov.b64 {%0,%1},%2;" : "=f"(lo), "=f"(hi) : "l"(a)); return lo + hi;
}
__device__ __forceinline__ u64 pack2(float lo, float hi) {
    u64 d; asm("mov.b64 %0,{%1,%2};" : "=l"(d) : "f"(lo), "f"(hi)); return d;
}
__device__ __forceinline__ u64 dup2(float x) {
    u64 d; asm("mov.b64 %0,{%1,%1};" : "=l"(d) : "f"(x)); return d;
}
__device__ __forceinline__ void unpack2(u64 a, float& lo, float& hi) {
    asm("mov.b64 {%0,%1},%2;" : "=f"(lo), "=f"(hi) : "l"(a));
}

// 10-elem dot of two packed-f32x2 quintets
__device__ __forceinline__ float dot5(const u64* a, const u64* b) {
    u64 x = fmul2(a[0], b[0]);
    x = ffma2(a[1], b[1], x);
    x = ffma2(a[2], b[2], x);
    x = ffma2(a[3], b[3], x);
    x = ffma2(a[4], b[4], x);
    return hsum2(x);
}

// Load compact chunk t (rows 2t, 2t+1 of a 10x10 compact matrix) as two
// packed rows ra[5], rb[5].  base must be 16B aligned; chunk = 5x LDS.128.
__device__ __forceinline__ void loadChunk(const float* base, int t, u64* ra, u64* rb) {
    const ulonglong2* p = reinterpret_cast<const ulonglong2*>(base + 20 * t);
    ulonglong2 q0 = p[0], q1 = p[1], q2 = p[2], q3 = p[3], q4 = p[4];
    ra[0] = q0.x; ra[1] = q0.y; ra[2] = q1.x; ra[3] = q1.y; ra[4] = q2.x;
    rb[0] = q2.y; rb[1] = q3.x; rb[2] = q3.y; rb[3] = q4.x; rb[4] = q4.y;
}

__global__ void __launch_bounds__(BLOCK, 6)
aie_kernel(const float* __restrict__ user_rep,
           const float* __restrict__ item_rep,
           const float* __restrict__ Mmat,
           const float* __restrict__ Pu,
           const float* __restrict__ pu_par,
           const float* __restrict__ Pi,
           const float* __restrict__ pi_par,
           float* __restrict__ out)
{
    __shared__ __align__(16) float Ms[104];                 // M compact (block-shared)
    __shared__ __align__(16) float Uc [WPB][104];           // U compact per warp
    __shared__ __align__(16) float Vc [WPB][104];           // V compact per warp
    __shared__ __align__(16) float AFc[WPB][104];           // aff (relu'd) compact rows (v packed)
    __shared__ __align__(16) float ST [WPB][20 * STSTRIDE]; // score transpose [20][32+pad]

    const int tid  = threadIdx.x;
    const int w    = tid >> 5;
    const int lane = tid & 31;

    // one-time: copy M into smem compact
    if (tid < 25) reinterpret_cast<float4*>(Ms)[tid] = reinterpret_cast<const float4*>(Mmat)[tid];
    __syncthreads();

    // persistent per-lane state (lane = k): projection rows packed over d
    u64 pu2[5], pi2[5];
    {
        const float* pr = Pu + lane * 10;
        const float* qr = Pi + lane * 10;
#pragma unroll
        for (int j = 0; j < 5; j++) {
            pu2[j] = pack2(pr[2 * j], pr[2 * j + 1]);
            pi2[j] = pack2(qr[2 * j], qr[2 * j + 1]);
        }
    }
    const float puk = pu_par[lane];
    const float pik = pi_par[lane];

    // score-reduction lane mapping: lanes 0-9 -> rows 0-9 (user), 16-25 -> rows 10-19 (item)
    const int sl = (lane < 10) ? lane : ((lane >= 16 && lane < 26) ? (lane - 6) : -1);

    const int gw     = blockIdx.x * WPB + w;
    const int stride = gridDim.x * WPB;
    const bool low10 = (lane < 10);

    float* Uw  = Uc[w];
    float* Vw  = Vc[w];
    float* AFw = AFc[w];
    float* STw = ST[w];

    for (int b = gw; b < BATCH; b += stride) {
        // ========== A: global -> compact smem (layout identical, no scatter) ==========
        if (lane < 25) {
            float4 uq = reinterpret_cast<const float4*>(user_rep + (size_t)b * 100)[lane];
            float4 vq = reinterpret_cast<const float4*>(item_rep + (size_t)b * 100)[lane];
            reinterpret_cast<float4*>(Uw)[lane] = uq;
            reinterpret_cast<float4*>(Vw)[lane] = vq;
        }
        __syncwarp();

        // ========== B (lanes 0-9): UM row u packed over e, via M-chunk accumulation ==========
        u64 um[5];
        {
            // own U row (5x LDS.64, 1 wavefront each)
            u64 ur[5];
            const u64* up = reinterpret_cast<const u64*>(Uw) + 5 * lane;
            if (low10) {
#pragma unroll
                for (int j = 0; j < 5; j++) ur[j] = up[j];
            }
            float us[10];
#pragma unroll
            for (int j = 0; j < 5; j++) unpack2(ur[j], us[2 * j], us[2 * j + 1]);
#pragma unroll
            for (int t = 0; t < 5; t++) {
                u64 ra[5], rb[5];
                loadChunk(Ms, t, ra, rb);           // M rows d=2t, 2t+1 (broadcast)
                u64 d0 = dup2(us[2 * t]);
                u64 d1 = dup2(us[2 * t + 1]);
                if (t == 0) {
#pragma unroll
                    for (int j = 0; j < 5; j++) um[j] = fmul2(d0, ra[j]);
                } else {
#pragma unroll
                    for (int j = 0; j < 5; j++) um[j] = ffma2(d0, ra[j], um[j]);
                }
#pragma unroll
                for (int j = 0; j < 5; j++) um[j] = ffma2(d1, rb[j], um[j]);
            }
        }

        // ========== D: hU[u] = dot(Pu[k,:], U[u,:])  (broadcast U chunks) ==========
        float hU[10];
#pragma unroll
        for (int t = 0; t < 5; t++) {
            u64 ra[5], rb[5];
            loadChunk(Uw, t, ra, rb);
            hU[2 * t]     = dot5(pu2, ra);
            hU[2 * t + 1] = dot5(pu2, rb);
        }

        // ========== C+E merged: V chunks -> hI (all lanes) + aff rows (lanes 0-9) ==========
        float hI[10];
        float aff[10];
#pragma unroll
        for (int t = 0; t < 5; t++) {
            u64 ra[5], rb[5];
            loadChunk(Vw, t, ra, rb);
            hI[2 * t]     = dot5(pi2, ra);
            hI[2 * t + 1] = dot5(pi2, rb);
            if (low10) {
                aff[2 * t]     = fmaxf(dot5(um, ra), 0.f);
                aff[2 * t + 1] = fmaxf(dot5(um, rb), 0.f);
            }
        }
        u64 hI2[5];
#pragma unroll
        for (int j = 0; j < 5; j++) hI2[j] = pack2(hI[2 * j], hI[2 * j + 1]);
        if (low10) {
            u64* afp = reinterpret_cast<u64*>(AFw) + 5 * lane;
#pragma unroll
            for (int j = 0; j < 5; j++) afp[j] = pack2(aff[2 * j], aff[2 * j + 1]);
        }
        __syncwarp();

        // ========== F+G merged: one pass over AF rows ==========
        // F: hu[u]  = relu(hU[u] + dot(hI, aff[u,:]))      (row dot)
        // G: hi[v] += hU[u] * aff[u][v]                    (packed accumulator over v)
        u64 hia[5];
#pragma unroll
        for (int t = 0; t < 5; t++) {
            u64 ra[5], rb[5];
            loadChunk(AFw, t, ra, rb);
            // F part
            float s0 = dot5(hI2, ra);
            float s1 = dot5(hI2, rb);
            float hu0 = fmaxf(hU[2 * t] + s0, 0.f);
            float hu1 = fmaxf(hU[2 * t + 1] + s1, 0.f);
            STw[(2 * t) * STSTRIDE + lane]     = puk * hu0;
            STw[(2 * t + 1) * STSTRIDE + lane] = puk * hu1;
            // G part
            u64 d0 = dup2(hU[2 * t]);
            u64 d1 = dup2(hU[2 * t + 1]);
            if (t == 0) {
#pragma unroll
                for (int j = 0; j < 5; j++) hia[j] = fmul2(d0, ra[j]);
            } else {
#pragma unroll
                for (int j = 0; j < 5; j++) hia[j] = ffma2(d0, ra[j], hia[j]);
            }
#pragma unroll
            for (int j = 0; j < 5; j++) hia[j] = ffma2(d1, rb[j], hia[j]);
        }
#pragma unroll
        for (int j = 0; j < 5; j++) {
            float lo, hi;
            unpack2(fadd2(hI2[j], hia[j]), lo, hi);
            STw[(10 + 2 * j) * STSTRIDE + lane]     = pik * fmaxf(lo, 0.f);
            STw[(10 + 2 * j + 1) * STSTRIDE + lane] = pik * fmaxf(hi, 0.f);
        }
        __syncwarp();

        // ========== H: reduce over k (32 lanes) via smem transpose + softmax ==========
        float score = -1e30f;
        if (sl >= 0) {
            const ulonglong2* q = reinterpret_cast<const ulonglong2*>(STw + sl * STSTRIDE);
            u64 t0 = fadd2(q[0].x, q[0].y);
            u64 t1 = fadd2(q[1].x, q[1].y);
            u64 t2 = fadd2(q[2].x, q[2].y);
            u64 t3 = fadd2(q[3].x, q[3].y);
            u64 t4 = fadd2(q[4].x, q[4].y);
            u64 t5 = fadd2(q[5].x, q[5].y);
            u64 t6 = fadd2(q[6].x, q[6].y);
            u64 t7 = fadd2(q[7].x, q[7].y);
            t0 = fadd2(t0, t1); t2 = fadd2(t2, t3);
            t4 = fadd2(t4, t5); t6 = fadd2(t6, t7);
            t0 = fadd2(t0, t2); t4 = fadd2(t4, t6);
            score = hsum2(fadd2(t0, t4));
        }

        // softmax within 16-lane subgroups (user: lanes 0-15, item: lanes 16-31)
        float mv = score;
#pragma unroll
        for (int msk = 8; msk; msk >>= 1)
            mv = fmaxf(mv, __shfl_xor_sync(0xffffffffu, mv, msk));
        float ev = __expf(score - mv);
        float sv = ev;
#pragma unroll
        for (int msk = 8; msk; msk >>= 1)
            sv += __shfl_xor_sync(0xffffffffu, sv, msk);
        float res = __fdividef(ev, sv);

        if (lane < 10)
            out[(size_t)b * 10 + lane] = res;
        else if (lane >= 16 && lane < 26)
            out[(size_t)BATCH * 10 + (size_t)b * 10 + (lane - 16)] = res;
        __syncwarp();
    }
}

extern "C" void kernel_launch(void* const* d_in, const int* in_sizes, int n_in,
                              void* d_out, int out_size) {
    const float* user_rep = (const float*)d_in[0];
    const float* item_rep = (const float*)d_in[1];
    const float* M        = (const float*)d_in[2];
    const float* Pu       = (const float*)d_in[3];
    const float* pu       = (const float*)d_in[4];
    const float* Pi       = (const float*)d_in[5];
    const float* pi       = (const float*)d_in[6];
    (void)in_sizes; (void)n_in; (void)out_size;
    aie_kernel<<<NBLOCKS, BLOCK>>>(user_rep, item_rep, M, Pu, pu, Pi, pi, (float*)d_out);
}

// round 6
// speedup vs baseline: 2.0637x; 1.4717x over previous
#include <cuda_runtime.h>

#define BATCH 262144
#define NPAIR (BATCH / 2)
#define NBLOCKS 8192
#define BLOCK 128
#define WPB 4
#define STSTRIDE 36

using u64 = unsigned long long;

__device__ __forceinline__ u64 fmul2(u64 a, u64 b) {
    u64 d; asm("mul.rn.f32x2 %0,%1,%2;" : "=l"(d) : "l"(a), "l"(b)); return d;
}
__device__ __forceinline__ u64 ffma2(u64 a, u64 b, u64 c) {
    u64 d; asm("fma.rn.f32x2 %0,%1,%2,%3;" : "=l"(d) : "l"(a), "l"(b), "l"(c)); return d;
}
__device__ __forceinline__ u64 fadd2(u64 a, u64 b) {
    u64 d; asm("add.rn.f32x2 %0,%1,%2;" : "=l"(d) : "l"(a), "l"(b)); return d;
}
__device__ __forceinline__ float hsum2(u64 a) {
    float lo, hi; asm("mov.b64 {%0,%1},%2;" : "=f"(lo), "=f"(hi) : "l"(a)); return lo + hi;
}
__device__ __forceinline__ u64 pack2(float lo, float hi) {
    u64 d; asm("mov.b64 %0,{%1,%2};" : "=l"(d) : "f"(lo), "f"(hi)); return d;
}
__device__ __forceinline__ u64 dup2(float x) {
    u64 d; asm("mov.b64 %0,{%1,%1};" : "=l"(d) : "f"(x)); return d;
}
__device__ __forceinline__ void unpack2(u64 a, float& lo, float& hi) {
    asm("mov.b64 {%0,%1},%2;" : "=f"(lo), "=f"(hi) : "l"(a));
}

__device__ __forceinline__ float dot5(const u64* a, const u64* b) {
    u64 x = fmul2(a[0], b[0]);
    x = ffma2(a[1], b[1], x);
    x = ffma2(a[2], b[2], x);
    x = ffma2(a[3], b[3], x);
    x = ffma2(a[4], b[4], x);
    return hsum2(x);
}

// rows 2t, 2t+1 of a compact 10x10 matrix -> two packed quintets (5x LDS.128)
__device__ __forceinline__ void loadChunk(const float* base, int t, u64* ra, u64* rb) {
    const ulonglong2* p = reinterpret_cast<const ulonglong2*>(base + 20 * t);
    ulonglong2 q0 = p[0], q1 = p[1], q2 = p[2], q3 = p[3], q4 = p[4];
    ra[0] = q0.x; ra[1] = q0.y; ra[2] = q1.x; ra[3] = q1.y; ra[4] = q2.x;
    rb[0] = q2.y; rb[1] = q3.x; rb[2] = q3.y; rb[3] = q4.x; rb[4] = q4.y;
}

__global__ void __launch_bounds__(BLOCK, 4)
aie_kernel(const float* __restrict__ user_rep,
           const float* __restrict__ item_rep,
           const float* __restrict__ Mmat,
           const float* __restrict__ Pu,
           const float* __restrict__ pu_par,
           const float* __restrict__ Pi,
           const float* __restrict__ pi_par,
           float* __restrict__ out)
{
    __shared__ __align__(16) float Ms[100];
    __shared__ __align__(16) float PuS[320];                // [k=32][10] floats == u64[32][5]
    __shared__ __align__(16) float PiS[320];
    __shared__ __align__(16) float Uc [WPB][200];           // 2 batches x 100, contiguous
    __shared__ __align__(16) float Vc [WPB][200];
    __shared__ __align__(16) float AFc[WPB][200];
    __shared__ __align__(16) float ST [WPB][20 * STSTRIDE]; // cols 0-15 batch0, 16-31 batch1

    const int tid  = threadIdx.x;
    const int w    = tid >> 5;
    const int lane = tid & 31;
    const int hl   = lane & 15;   // lane within half: k0 = hl, k1 = hl+16
    const int half = lane >> 4;   // which batch of the pair

    // one-time: stage constants into smem
    if (tid < 25) reinterpret_cast<float4*>(Ms)[tid] = reinterpret_cast<const float4*>(Mmat)[tid];
    if (tid < 80) {
        reinterpret_cast<float4*>(PuS)[tid] = reinterpret_cast<const float4*>(Pu)[tid];
        reinterpret_cast<float4*>(PiS)[tid] = reinterpret_cast<const float4*>(Pi)[tid];
    }
    __syncthreads();

    const float puk0 = pu_par[hl];
    const float puk1 = pu_par[hl + 16];
    const float pik0 = pi_par[hl];
    const float pik1 = pi_par[hl + 16];

    const bool low10 = (hl < 10);
    const int  srow  = (lane < 10) ? lane : ((lane >= 16 && lane < 26) ? (lane - 6) : -1);

    float* Uw  = Uc[w];
    float* Vw  = Vc[w];
    float* AFw = AFc[w];
    float* STw = ST[w];
    const float* myU  = Uw  + half * 100;
    const float* myV  = Vw  + half * 100;
    const float* myAF = AFw + half * 100;
    float* myAFst = AFw + half * 100;

    const u64* PuS64 = reinterpret_cast<const u64*>(PuS);
    const u64* PiS64 = reinterpret_cast<const u64*>(PiS);

    const int gw     = blockIdx.x * WPB + w;
    const int stride = gridDim.x * WPB;

    for (int it = gw; it < NPAIR; it += stride) {
        // ========== A: load 2 batches of U,V (contiguous 800B each) ==========
        {
            const float4* ug = reinterpret_cast<const float4*>(user_rep) + (size_t)it * 50;
            const float4* vg = reinterpret_cast<const float4*>(item_rep) + (size_t)it * 50;
            float4 u0 = ug[lane];
            float4 v0 = vg[lane];
            reinterpret_cast<float4*>(Uw)[lane] = u0;
            reinterpret_cast<float4*>(Vw)[lane] = v0;
            if (lane < 18) {
                float4 u1 = ug[lane + 32];
                float4 v1 = vg[lane + 32];
                reinterpret_cast<float4*>(Uw)[lane + 32] = u1;
                reinterpret_cast<float4*>(Vw)[lane + 32] = v1;
            }
        }
        __syncwarp();

        // ========== B: UM row u=hl (lanes hl<10 of each half), M broadcast ==========
        u64 um[5];
        {
            float us[10];
            if (low10) {
                const u64* up = reinterpret_cast<const u64*>(myU + hl * 10);
#pragma unroll
                for (int j = 0; j < 5; j++) unpack2(up[j], us[2 * j], us[2 * j + 1]);
            }
#pragma unroll
            for (int t = 0; t < 5; t++) {
                u64 ra[5], rb[5];
                loadChunk(Ms, t, ra, rb);
                u64 d0 = dup2(us[2 * t]);
                u64 d1 = dup2(us[2 * t + 1]);
                if (t == 0) {
#pragma unroll
                    for (int j = 0; j < 5; j++) um[j] = fmul2(d0, ra[j]);
                } else {
#pragma unroll
                    for (int j = 0; j < 5; j++) um[j] = ffma2(d0, ra[j], um[j]);
                }
#pragma unroll
                for (int j = 0; j < 5; j++) um[j] = ffma2(d1, rb[j], um[j]);
            }
        }

        // ========== D: hU for k0, k1 (U chunks, 2-address broadcast) ==========
        float hU0[10], hU1[10];
        {
            u64 pA[5], pB[5];
            const u64* ps = PuS64 + hl * 5;
#pragma unroll
            for (int j = 0; j < 5; j++) { pA[j] = ps[j]; pB[j] = ps[j + 80]; }
#pragma unroll
            for (int t = 0; t < 5; t++) {
                u64 ra[5], rb[5];
                loadChunk(myU, t, ra, rb);
                hU0[2 * t]     = dot5(pA, ra);
                hU0[2 * t + 1] = dot5(pA, rb);
                hU1[2 * t]     = dot5(pB, ra);
                hU1[2 * t + 1] = dot5(pB, rb);
            }
        }

        // ========== C+E: V chunks -> hI (k0,k1) + aff rows (lanes hl<10) ==========
        float hI0[10], hI1[10], aff[10];
        {
            u64 pA[5], pB[5];
            const u64* ps = PiS64 + hl * 5;
#pragma unroll
            for (int j = 0; j < 5; j++) { pA[j] = ps[j]; pB[j] = ps[j + 80]; }
#pragma unroll
            for (int t = 0; t < 5; t++) {
                u64 ra[5], rb[5];
                loadChunk(myV, t, ra, rb);
                hI0[2 * t]     = dot5(pA, ra);
                hI0[2 * t + 1] = dot5(pA, rb);
                hI1[2 * t]     = dot5(pB, ra);
                hI1[2 * t + 1] = dot5(pB, rb);
                if (low10) {
                    aff[2 * t]     = fmaxf(dot5(um, ra), 0.f);
                    aff[2 * t + 1] = fmaxf(dot5(um, rb), 0.f);
                }
            }
        }
        u64 hI20[5], hI21[5];
#pragma unroll
        for (int j = 0; j < 5; j++) {
            hI20[j] = pack2(hI0[2 * j], hI0[2 * j + 1]);
            hI21[j] = pack2(hI1[2 * j], hI1[2 * j + 1]);
        }
        if (low10) {
            u64* afp = reinterpret_cast<u64*>(myAFst + hl * 10);
#pragma unroll
            for (int j = 0; j < 5; j++) afp[j] = pack2(aff[2 * j], aff[2 * j + 1]);
        }
        __syncwarp();

        // ========== F+G: one pass over AF chunks ==========
        u64 hiaA[5], hiaB[5];
#pragma unroll
        for (int t = 0; t < 5; t++) {
            u64 ra[5], rb[5];
            loadChunk(myAF, t, ra, rb);
            // F: user branch, both k
            float s0a = dot5(hI20, ra), s1a = dot5(hI20, rb);
            float s0b = dot5(hI21, ra), s1b = dot5(hI21, rb);
            float hu0a = fmaxf(hU0[2 * t]     + s0a, 0.f);
            float hu1a = fmaxf(hU0[2 * t + 1] + s1a, 0.f);
            float hu0b = fmaxf(hU1[2 * t]     + s0b, 0.f);
            float hu1b = fmaxf(hU1[2 * t + 1] + s1b, 0.f);
            STw[(2 * t) * STSTRIDE + lane]     = puk0 * hu0a + puk1 * hu0b;
            STw[(2 * t + 1) * STSTRIDE + lane] = puk0 * hu1a + puk1 * hu1b;
            // G: item accumulators, both k
            u64 dA0 = dup2(hU0[2 * t]), dA1 = dup2(hU0[2 * t + 1]);
            u64 dB0 = dup2(hU1[2 * t]), dB1 = dup2(hU1[2 * t + 1]);
            if (t == 0) {
#pragma unroll
                for (int j = 0; j < 5; j++) { hiaA[j] = fmul2(dA0, ra[j]); hiaB[j] = fmul2(dB0, ra[j]); }
            } else {
#pragma unroll
                for (int j = 0; j < 5; j++) { hiaA[j] = ffma2(dA0, ra[j], hiaA[j]); hiaB[j] = ffma2(dB0, ra[j], hiaB[j]); }
            }
#pragma unroll
            for (int j = 0; j < 5; j++) { hiaA[j] = ffma2(dA1, rb[j], hiaA[j]); hiaB[j] = ffma2(dB1, rb[j], hiaB[j]); }
        }
#pragma unroll
        for (int j = 0; j < 5; j++) {
            float loA, hiA, loB, hiB;
            unpack2(fadd2(hI20[j], hiaA[j]), loA, hiA);
            unpack2(fadd2(hI21[j], hiaB[j]), loB, hiB);
            STw[(10 + 2 * j) * STSTRIDE + lane] = pik0 * fmaxf(loA, 0.f) + pik1 * fmaxf(loB, 0.f);
            STw[(11 + 2 * j) * STSTRIDE + lane] = pik0 * fmaxf(hiA, 0.f) + pik1 * fmaxf(hiB, 0.f);
        }
        __syncwarp();

        // ========== H: per-batch k-reduction + softmax (two passes) ==========
#pragma unroll
        for (int p = 0; p < 2; p++) {
            float score = -1e30f;
            if (srow >= 0) {
                const ulonglong2* q = reinterpret_cast<const ulonglong2*>(STw + srow * STSTRIDE + p * 16);
                ulonglong2 a = q[0], b2 = q[1];
                score = hsum2(fadd2(fadd2(a.x, a.y), fadd2(b2.x, b2.y)));
            }
            float mv = score;
#pragma unroll
            for (int msk = 8; msk; msk >>= 1)
                mv = fmaxf(mv, __shfl_xor_sync(0xffffffffu, mv, msk));
            float ev = __expf(score - mv);
            float sv = ev;
#pragma unroll
            for (int msk = 8; msk; msk >>= 1)
                sv += __shfl_xor_sync(0xffffffffu, sv, msk);
            float res = __fdividef(ev, sv);

            size_t b = 2 * (size_t)it + p;
            if (lane < 10)
                out[b * 10 + lane] = res;
            else if (srow >= 0)
                out[(size_t)BATCH * 10 + b * 10 + (lane - 16)] = res;
        }
        __syncwarp();
    }
}

extern "C" void kernel_launch(void* const* d_in, const int* in_sizes, int n_in,
                              void* d_out, int out_size) {
    const float* user_rep = (const float*)d_in[0];
    const float* item_rep = (const float*)d_in[1];
    const float* M        = (const float*)d_in[2];
    const float* Pu       = (const float*)d_in[3];
    const float* pu       = (const float*)d_in[4];
    const float* Pi       = (const float*)d_in[5];
    const float* pi       = (const float*)d_in[6];
    (void)in_sizes; (void)n_in; (void)out_size;
    aie_kernel<<<NBLOCKS, BLOCK>>>(user_rep, item_rep, M, Pu, pu, Pi, pi, (float*)d_out);
}